// round 16
// baseline (speedup 1.0000x reference)
#include <cuda_runtime.h>
#include <cuda_bf16.h>
#include <math.h>
#include <stdint.h>

#define BATCH 16384
#define HID 256

// Output layout (float32):
//   [0, 4194304)            h_next  (B,1,256)
//   [4194304, 4194313)      G_structure (9 floats)
//   [4194313, 41943049)     G_node  (B,9,256)   <-- base NOT 16B-aligned (offset 9 floats)
//   [41943049, 41943055)    margins (6)
#define OFF_GS 4194304ul
#define OFF_GN 4194313ul
#define OFF_MG 41943049ul
#define GN_LD  2304

// ---------------------------------------------------------------------------
// Scratch (device globals). 16B-aligned (vector access).
// 5 product buffers (B x 768), lifetime-multiplexed:
//   P1: x@L -> ht@L        P2: h@R(512) -> r@R -> rh@R -> (zht@L + z2h@R) fused
//   P3: h@L                P4: z1@R
//   P5: omz@R
// ---------------------------------------------------------------------------
__device__ __align__(16) float g_p1[(size_t)BATCH * 768];
__device__ __align__(16) float g_p2[(size_t)BATCH * 768];
__device__ __align__(16) float g_p3[(size_t)BATCH * 768];
__device__ __align__(16) float g_p4[(size_t)BATCH * 768];
__device__ __align__(16) float g_p5[(size_t)BATCH * 768];
__device__ __align__(16) float g_z1 [(size_t)BATCH * HID];
__device__ __align__(16) float g_r  [(size_t)BATCH * HID];
__device__ __align__(16) float g_rh [(size_t)BATCH * HID];
__device__ __align__(16) float g_ht [(size_t)BATCH * HID];
__device__ __align__(16) float g_omz[(size_t)BATCH * HID];
__device__ __align__(16) float g_zht[(size_t)BATCH * HID];
__device__ __align__(16) float g_z2h[(size_t)BATCH * HID];
__device__ double g_ssum[24];

// split-bf16 activations (hi/lo)
#define ACT_ELEMS ((size_t)BATCH * HID)
__device__ __align__(16) __nv_bfloat16 g_xhi[ACT_ELEMS],  g_xlo[ACT_ELEMS];
__device__ __align__(16) __nv_bfloat16 g_hhi[ACT_ELEMS],  g_hlo[ACT_ELEMS];
__device__ __align__(16) __nv_bfloat16 g_z1hi[ACT_ELEMS], g_z1lo[ACT_ELEMS];
__device__ __align__(16) __nv_bfloat16 g_rhi[ACT_ELEMS],  g_rlo[ACT_ELEMS];
__device__ __align__(16) __nv_bfloat16 g_rhhi[ACT_ELEMS], g_rhlo[ACT_ELEMS];
__device__ __align__(16) __nv_bfloat16 g_hthi[ACT_ELEMS], g_htlo[ACT_ELEMS];
__device__ __align__(16) __nv_bfloat16 g_omzhi[ACT_ELEMS],g_omzlo[ACT_ELEMS];
__device__ __align__(16) __nv_bfloat16 g_zhthi[ACT_ELEMS],g_zhtlo[ACT_ELEMS];
__device__ __align__(16) __nv_bfloat16 g_z2hhi[ACT_ELEMS],g_z2hlo[ACT_ELEMS];

// split-bf16 weights, transposed [slab][n][k], slabs 0..2
#define W_ELEMS (3 * 65536)
__device__ __align__(16) __nv_bfloat16 g_WLhi[W_ELEMS], g_WLlo[W_ELEMS];
__device__ __align__(16) __nv_bfloat16 g_WRhi[W_ELEMS], g_WRlo[W_ELEMS];

__global__ void init_kernel() {
    int t = threadIdx.x;
    if (t < 24) g_ssum[t] = 0.0;
}

// W[s][k][n] fp32 -> hi/lo[s][n][k] bf16 (slabs 0..2); z: 0=L, 1=R
__global__ void prep_w(const float* __restrict__ WL, const float* __restrict__ WR,
                       __nv_bfloat16* __restrict__ hiL, __nv_bfloat16* __restrict__ loL,
                       __nv_bfloat16* __restrict__ hiR, __nv_bfloat16* __restrict__ loR) {
    const float* W = blockIdx.z ? WR : WL;
    __nv_bfloat16* hi = blockIdx.z ? hiR : hiL;
    __nv_bfloat16* lo = blockIdx.z ? loR : loL;
    int i = blockIdx.x * 256 + threadIdx.x;          // s*65536 + k*256 + n
    int s = i >> 16, rem = i & 65535, k = rem >> 8, n = rem & 255;
    float v = W[i];
    __nv_bfloat16 h = __float2bfloat16(v);
    size_t o = (size_t)s * 65536 + (size_t)n * 256 + k;
    hi[o] = h;
    lo[o] = __float2bfloat16(v - __bfloat162float(h));
}

// z: 0=x, 1=h
__global__ void prep_a(const float* __restrict__ X, const float* __restrict__ H,
                       __nv_bfloat16* __restrict__ xhi, __nv_bfloat16* __restrict__ xlo,
                       __nv_bfloat16* __restrict__ hhi, __nv_bfloat16* __restrict__ hlo) {
    const float* A = blockIdx.z ? H : X;
    __nv_bfloat16* hi = blockIdx.z ? hhi : xhi;
    __nv_bfloat16* lo = blockIdx.z ? hlo : xlo;
    size_t i = (size_t)blockIdx.x * 256 + threadIdx.x;
    float v = A[i];
    __nv_bfloat16 h = __float2bfloat16(v);
    hi[i] = h;
    lo[i] = __float2bfloat16(v - __bfloat162float(h));
}

// ---------------------------------------------------------------------------
// Raw tensor-core GEMM (bf16 mma.sync, fp32 accum), 3-term split:
//   C = Ahi@Whi + Alo@Whi + Ahi@Wlo   (12 chunks / operand pair)
// Optional second pair (A2/B2, nch=24) accumulates into the same output
// (used for fused zht@L + z2h@R). nx = active x-blocks (truncated N).
// Output raw fp32, ldc=768. CTA 128x128, 8 warps, 2-stage cp.async.
// blockIdx.z selects one of up to 3 argument sets.
// ---------------------------------------------------------------------------
#define SROW 144
#define SAB  18432
#define SMEM_TOT (4 * SAB)

struct GR {
    const __nv_bfloat16 *Ahi, *Alo, *Bhi, *Blo;
    const __nv_bfloat16 *A2hi, *A2lo, *B2hi, *B2lo;
    float* C;
    int nx, nch;
};

__device__ __forceinline__ uint32_t smem_u32(const void* p) {
    uint32_t a;
    asm("{ .reg .u64 t; cvta.to.shared.u64 t, %1; cvt.u32.u64 %0, t; }" : "=r"(a) : "l"(p));
    return a;
}
#define CP_ASYNC16(dst, src) \
    asm volatile("cp.async.cg.shared.global [%0], [%1], 16;" :: "r"(dst), "l"(src))
#define CP_COMMIT() asm volatile("cp.async.commit_group;")
#define LDSM_X4(r, addr) \
    asm volatile("ldmatrix.sync.aligned.m8n8.x4.shared.b16 {%0,%1,%2,%3}, [%4];" \
        : "=r"((r)[0]), "=r"((r)[1]), "=r"((r)[2]), "=r"((r)[3]) : "r"(addr))
#define MMA16816(c, a, b0, b1) \
    asm volatile("mma.sync.aligned.m16n8k16.row.col.f32.bf16.bf16.f32 " \
        "{%0,%1,%2,%3}, {%4,%5,%6,%7}, {%8,%9}, {%0,%1,%2,%3};" \
        : "+f"((c)[0]), "+f"((c)[1]), "+f"((c)[2]), "+f"((c)[3]) \
        : "r"((a)[0]), "r"((a)[1]), "r"((a)[2]), "r"((a)[3]), "r"(b0), "r"(b1))

__global__ void __launch_bounds__(256, 2) mma_raw(GR g0, GR g1, GR g2)
{
    const GR& G = (blockIdx.z == 0) ? g0 : (blockIdx.z == 1) ? g1 : g2;
    if ((int)blockIdx.x >= G.nx) return;
    extern __shared__ __align__(16) char smem[];
    const int tid = threadIdx.x, wid = tid >> 5, lane = tid & 31;
    const int wm = wid >> 2, wn = wid & 3;
    const int bm0 = blockIdx.y * 128;
    const int nglob = blockIdx.x * 128;
    const int slab = nglob >> 8, nr = nglob & 255;
    const uint32_t sb = smem_u32(smem);
    const int NCH = G.nch;

    const int lr = tid >> 1, lh = tid & 1;
    const size_t gArow = (size_t)(bm0 + lr) * 256 + lh * 32;
    const size_t gBrow = (size_t)slab * 65536 + (size_t)(nr + lr) * 256 + lh * 32;
    const uint32_t sOff = lr * SROW + lh * 64;

    auto issue = [&](int c) {
        const int p = (c >= 12) ? 1 : 0;
        const int cc = c - 12 * p;
        const int seg = cc >> 2;
        const int k0 = (cc & 3) * 64;
        const __nv_bfloat16* gA = (seg == 1) ? (p ? G.A2lo : G.Alo) : (p ? G.A2hi : G.Ahi);
        const __nv_bfloat16* gB = (seg == 2) ? (p ? G.B2lo : G.Blo) : (p ? G.B2hi : G.Bhi);
        const char* srcA = (const char*)(gA + gArow + k0);
        const char* srcB = (const char*)(gB + gBrow + k0);
        const int buf = c & 1;
        uint32_t dA = sb + buf * 2 * SAB + sOff;
        uint32_t dB = sb + buf * 2 * SAB + SAB + sOff;
        #pragma unroll
        for (int i = 0; i < 4; i++) CP_ASYNC16(dA + i * 16, srcA + i * 16);
        #pragma unroll
        for (int i = 0; i < 4; i++) CP_ASYNC16(dB + i * 16, srcB + i * 16);
    };

    float acc[4][4][4];
    #pragma unroll
    for (int i = 0; i < 4; i++)
        #pragma unroll
        for (int j = 0; j < 4; j++)
            #pragma unroll
            for (int t = 0; t < 4; t++) acc[i][j][t] = 0.f;

    const uint32_t aLane = (lane & 15) * SROW + (lane >> 4) * 16;
    const uint32_t bLane = ((lane & 7) + ((lane >= 16) ? 8 : 0)) * SROW + ((lane >> 3) & 1) * 16;

    issue(0); CP_COMMIT();

    #pragma unroll 1
    for (int c = 0; c < NCH; c++) {
        asm volatile("cp.async.wait_group 0;");
        __syncthreads();
        if (c + 1 < NCH) { issue(c + 1); CP_COMMIT(); }

        const int buf = c & 1;
        const uint32_t aBase = sb + buf * 2 * SAB + (wm * 64) * SROW + aLane;
        const uint32_t bBase = sb + buf * 2 * SAB + SAB + (wn * 32) * SROW + bLane;

        uint32_t a[2][4][4], bfr[2][2][4];
        #pragma unroll
        for (int np = 0; np < 2; np++)
            LDSM_X4(bfr[0][np], bBase + np * 16 * SROW);
        #pragma unroll
        for (int mt = 0; mt < 4; mt++)
            LDSM_X4(a[0][mt], aBase + mt * 16 * SROW);

        #pragma unroll
        for (int ks = 0; ks < 4; ks++) {
            const int cur = ks & 1, nxt = cur ^ 1;
            if (ks < 3) {
                #pragma unroll
                for (int np = 0; np < 2; np++)
                    LDSM_X4(bfr[nxt][np], bBase + np * 16 * SROW + (ks + 1) * 32);
                #pragma unroll
                for (int mt = 0; mt < 4; mt++)
                    LDSM_X4(a[nxt][mt], aBase + mt * 16 * SROW + (ks + 1) * 32);
            }
            #pragma unroll
            for (int mt = 0; mt < 4; mt++)
                #pragma unroll
                for (int nt = 0; nt < 4; nt++)
                    MMA16816(acc[mt][nt], a[cur][mt],
                             bfr[cur][nt >> 1][(nt & 1) * 2],
                             bfr[cur][nt >> 1][(nt & 1) * 2 + 1]);
        }
    }

    // Epilogue: raw fp32 store, ldc=768
    const int lr4 = lane >> 2, lc2 = (lane & 3) * 2;
    #pragma unroll
    for (int mt = 0; mt < 4; mt++) {
        #pragma unroll
        for (int nt = 0; nt < 4; nt++) {
            const int row0 = bm0 + wm * 64 + mt * 16 + lr4;
            const int gcol = nglob + wn * 32 + nt * 8 + lc2;
            #pragma unroll
            for (int half = 0; half < 2; half++) {
                const int row = row0 + half * 8;
                float2 v = make_float2(acc[mt][nt][half * 2 + 0],
                                       acc[mt][nt][half * 2 + 1]);
                *(float2*)(G.C + (size_t)row * 768 + gcol) = v;
            }
        }
    }
}

// ---------------------------------------------------------------------------
// z1 & r from raw product slices.
// ---------------------------------------------------------------------------
__global__ void __launch_bounds__(256) z1r_kernel(
    const float* __restrict__ xL, const float* __restrict__ hR,
    const float* __restrict__ bias, float* __restrict__ gnode)
{
    size_t idx = (size_t)blockIdx.x * 256 + threadIdx.x;
    size_t b_ = idx >> 8;
    int d = (int)(idx & 255);
    size_t base = b_ * 768;

    float v0 = xL[base + d] + hR[base + d] + bias[d];
    float z1 = 1.f / (1.f + expf(-v0));
    g_z1[b_ * HID + d] = z1;
    gnode[b_ * GN_LD + 0 * HID + d] = z1;
    gnode[b_ * GN_LD + 2 * HID + d] = z1;
    __nv_bfloat16 zh = __float2bfloat16(z1);
    g_z1hi[b_ * HID + d] = zh;
    g_z1lo[b_ * HID + d] = __float2bfloat16(z1 - __bfloat162float(zh));

    float v1 = xL[base + 256 + d] + hR[base + 256 + d] + bias[256 + d];
    float r = 1.f / (1.f + expf(-v1));
    g_r[b_ * HID + d] = r;
    gnode[b_ * GN_LD + 1 * HID + d] = r;
    __nv_bfloat16 rh_ = __float2bfloat16(r);
    g_rhi[b_ * HID + d] = rh_;
    g_rlo[b_ * HID + d] = __float2bfloat16(r - __bfloat162float(rh_));
}

// ---------------------------------------------------------------------------
// Mixture over 4 candidates from RAW product buffers:
//   mode 0: c[k] = cand[k] + cand2[k] + ball[k];  k3 = a1 + a2 + b3
//   mode 1: c[k] = cand[k] * cand2[k] + ball[k];  k3 = a1*a2 + b3
//   mode 4: c[k] = 1 - (cand[k] + ball[k]);       k3 = 1 - (a1 + b3)
//   mode 5: c[k] = cand[k] + ball[k] (pre-summed);k3 = a1 + a2 + b3
// blockIdx.z selects one of 3 arg sets.
// ---------------------------------------------------------------------------
struct MArgs {
    const float *A1, *A2, *cand, *cand2, *ball;
    float* out1; int ld1;
    float* out2; int ld2;
    __nv_bfloat16 *Ohi, *Olo;
    int mode, stage;
};

__global__ void __launch_bounds__(256) mixture3_kernel(
    const float* __restrict__ Wsv, MArgs m0, MArgs m1, MArgs m2)
{
    const MArgs& M = (blockIdx.z == 0) ? m0 : (blockIdx.z == 1) ? m1 : m2;
    __shared__ float sWs[256];
    __shared__ float sSc[8][4];
    int tid = threadIdx.x;
    sWs[tid] = Wsv[tid];
    __syncthreads();

    int warp = tid >> 5, lane = tid & 31;
    size_t b = (size_t)blockIdx.x * 8 + warp;
    const float* crow  = M.cand + b * 768;
    const float* crow2 = (M.mode <= 1) ? (M.cand2 + b * 768) : nullptr;
    const float* bias3 = M.ball + 768;

    float c[4][8];
    #pragma unroll
    for (int k = 0; k < 3; k++)
        #pragma unroll
        for (int j = 0; j < 8; j++) {
            int d = j * 32 + lane;
            float v = crow[k * 256 + d];
            if (M.mode == 0)      v = v + crow2[k * 256 + d] + M.ball[k * 256 + d];
            else if (M.mode == 1) v = v * crow2[k * 256 + d] + M.ball[k * 256 + d];
            else if (M.mode == 4) v = 1.f - (v + M.ball[k * 256 + d]);
            else                  v = v + M.ball[k * 256 + d];
            c[k][j] = v;
        }

    #pragma unroll
    for (int j = 0; j < 8; j++) {
        int d = j * 32 + lane;
        float a1 = M.A1[b * HID + d];
        float v;
        if (M.mode == 0 || M.mode == 5) v = a1 + M.A2[b * HID + d] + bias3[d];
        else if (M.mode == 1)           v = a1 * M.A2[b * HID + d] + bias3[d];
        else                            v = 1.f - (a1 + bias3[d]);
        c[3][j] = v;
    }

    float sc[4];
    #pragma unroll
    for (int k = 0; k < 4; k++) {
        float p = 0.f;
        #pragma unroll
        for (int j = 0; j < 8; j++) p += c[k][j] * sWs[j * 32 + lane];
        #pragma unroll
        for (int o = 16; o > 0; o >>= 1) p += __shfl_xor_sync(0xffffffffu, p, o);
        sc[k] = p;
    }

    float mx = fmaxf(fmaxf(sc[0], sc[1]), fmaxf(sc[2], sc[3]));
    float e0 = expf(sc[0] - mx), e1 = expf(sc[1] - mx);
    float e2 = expf(sc[2] - mx), e3 = expf(sc[3] - mx);
    float inv = 1.f / (e0 + e1 + e2 + e3);

    #pragma unroll
    for (int j = 0; j < 8; j++) {
        int d = j * 32 + lane;
        float o = (e0 * c[0][j] + e1 * c[1][j] + e2 * c[2][j] + e3 * c[3][j]) * inv;
        M.out1[b * M.ld1 + d] = o;
        if (M.out2) M.out2[b * M.ld2 + d] = o;
        if (M.Ohi) {
            __nv_bfloat16 hv = __float2bfloat16(o);
            M.Ohi[b * HID + d] = hv;
            M.Olo[b * HID + d] = __float2bfloat16(o - __bfloat162float(hv));
        }
    }

    if (lane == 0) {
        sSc[warp][0] = sc[0]; sSc[warp][1] = sc[1];
        sSc[warp][2] = sc[2]; sSc[warp][3] = sc[3];
    }
    __syncthreads();
    if (tid < 4) {
        float s = 0.f;
        #pragma unroll
        for (int w = 0; w < 8; w++) s += sSc[w][tid];
        atomicAdd(&g_ssum[M.stage * 4 + tid], (double)s);
    }
}

__global__ void finalize_kernel(float* __restrict__ out) {
    if (threadIdx.x == 0 && blockIdx.x == 0) {
        float* gs = out + OFF_GS;
        float* mg = out + OFF_MG;
        gs[0] = 0.f; gs[1] = 1.f; gs[2] = 0.f;
        for (int s = 0; s < 6; s++) {
            double v[4];
            for (int k = 0; k < 4; k++) v[k] = g_ssum[s * 4 + k];
            int idx = 0; double m1 = v[0];
            for (int k = 1; k < 4; k++) if (v[k] > m1) { m1 = v[k]; idx = k; }
            double m2 = -1e300;
            for (int k = 0; k < 4; k++) if (k != idx && v[k] > m2) m2 = v[k];
            gs[3 + s] = (float)idx;
            mg[s] = (float)(m1 - m2);
        }
    }
}

// ---------------------------------------------------------------------------
extern "C" void kernel_launch(void* const* d_in, const int* in_sizes, int n_in,
                              void* d_out, int out_size) {
    const float* x  = (const float*)d_in[0];
    const float* h  = (const float*)d_in[1];
    const float* L  = (const float*)d_in[2];
    const float* R  = (const float*)d_in[3];
    const float* b  = (const float*)d_in[4];
    const float* Ws = (const float*)d_in[5];
    float* out = (float*)d_out;
    float* gnode = out + OFF_GN;

    float *z1p, *rp, *rhp, *htp, *omzp, *zhtp, *z2hp, *P1, *P2, *P3, *P4, *P5;
    cudaGetSymbolAddress((void**)&z1p,  g_z1);
    cudaGetSymbolAddress((void**)&rp,   g_r);
    cudaGetSymbolAddress((void**)&rhp,  g_rh);
    cudaGetSymbolAddress((void**)&htp,  g_ht);
    cudaGetSymbolAddress((void**)&omzp, g_omz);
    cudaGetSymbolAddress((void**)&zhtp, g_zht);
    cudaGetSymbolAddress((void**)&z2hp, g_z2h);
    cudaGetSymbolAddress((void**)&P1, g_p1);
    cudaGetSymbolAddress((void**)&P2, g_p2);
    cudaGetSymbolAddress((void**)&P3, g_p3);
    cudaGetSymbolAddress((void**)&P4, g_p4);
    cudaGetSymbolAddress((void**)&P5, g_p5);

    __nv_bfloat16 *xhi,*xlo,*hhi,*hlo,*z1hi,*z1lo,*rhi,*rlo,*rhhi,*rhlo,
                  *hthi,*htlo,*omzhi,*omzlo,*zhthi,*zhtlo,*z2hhi,*z2hlo,
                  *WLhi,*WLlo,*WRhi,*WRlo;
    cudaGetSymbolAddress((void**)&xhi, g_xhi);   cudaGetSymbolAddress((void**)&xlo, g_xlo);
    cudaGetSymbolAddress((void**)&hhi, g_hhi);   cudaGetSymbolAddress((void**)&hlo, g_hlo);
    cudaGetSymbolAddress((void**)&z1hi, g_z1hi); cudaGetSymbolAddress((void**)&z1lo, g_z1lo);
    cudaGetSymbolAddress((void**)&rhi, g_rhi);   cudaGetSymbolAddress((void**)&rlo, g_rlo);
    cudaGetSymbolAddress((void**)&rhhi, g_rhhi); cudaGetSymbolAddress((void**)&rhlo, g_rhlo);
    cudaGetSymbolAddress((void**)&hthi, g_hthi); cudaGetSymbolAddress((void**)&htlo, g_htlo);
    cudaGetSymbolAddress((void**)&omzhi, g_omzhi); cudaGetSymbolAddress((void**)&omzlo, g_omzlo);
    cudaGetSymbolAddress((void**)&zhthi, g_zhthi); cudaGetSymbolAddress((void**)&zhtlo, g_zhtlo);
    cudaGetSymbolAddress((void**)&z2hhi, g_z2hhi); cudaGetSymbolAddress((void**)&z2hlo, g_z2hlo);
    cudaGetSymbolAddress((void**)&WLhi, g_WLhi); cudaGetSymbolAddress((void**)&WLlo, g_WLlo);
    cudaGetSymbolAddress((void**)&WRhi, g_WRhi); cudaGetSymbolAddress((void**)&WRlo, g_WRlo);

    cudaFuncSetAttribute(mma_raw, cudaFuncAttributeMaxDynamicSharedMemorySize, SMEM_TOT);

    dim3 blk(256);
    int mixGrid = BATCH / 8;

    init_kernel<<<1, 32>>>();
    prep_w<<<dim3(768, 1, 2), 256>>>(L, R, WLhi, WLlo, WRhi, WRlo);
    prep_a<<<dim3(BATCH * HID / 256, 1, 2), 256>>>(x, h, xhi, xlo, hhi, hlo);

    const __nv_bfloat16* NB = nullptr;

    // Batch A: x@L -> P1 (full), h@R -> P2 (slabs 0,1), h@L -> P3 (full)
    {
        GR a0 = {xhi, xlo, WLhi, WLlo, NB, NB, NB, NB, P1, 6, 12};
        GR a1 = {hhi, hlo, WRhi, WRlo, NB, NB, NB, NB, P2, 4, 12};
        GR a2 = {hhi, hlo, WLhi, WLlo, NB, NB, NB, NB, P3, 6, 12};
        mma_raw<<<dim3(6, BATCH / 128, 3), blk, SMEM_TOT>>>(a0, a1, a2);
    }
    // z1 & r from slices of P1/P2
    z1r_kernel<<<BATCH, 256>>>(P1, P2, b, gnode);

    // Batch B: r@R -> P2 (reuse), z1@R -> P4
    {
        GR b0 = {rhi, rlo, WRhi, WRlo, NB, NB, NB, NB, P2, 6, 12};
        GR b1 = {z1hi, z1lo, WRhi, WRlo, NB, NB, NB, NB, P4, 6, 12};
        mma_raw<<<dim3(6, BATCH / 128, 2), blk, SMEM_TOT>>>(b0, b1, b0);
    }
    // M1 (3 slices): rh [P3+P2], omz [1-(P4+b)], z2h [P3*P4]
    {
        MArgs m0 = {h, rp, P3, P2, b, rhp, HID, gnode + 3 * HID, GN_LD, rhhi, rhlo, 0, 0};
        MArgs m1 = {z1p, nullptr, P4, nullptr, b, omzp, HID, gnode + 5 * HID, GN_LD,
                    omzhi, omzlo, 4, 2};
        MArgs m2 = {h, z1p, P3, P4, b, z2hp, HID, gnode + 7 * HID, GN_LD,
                    z2hhi, z2hlo, 1, 4};
        mixture3_kernel<<<dim3(mixGrid, 1, 3), 256>>>(Ws, m0, m1, m2);
    }
    // Batch C: rh@R -> P2 (reuse), omz@R -> P5
    {
        GR c0 = {rhhi, rhlo, WRhi, WRlo, NB, NB, NB, NB, P2, 6, 12};
        GR c1 = {omzhi, omzlo, WRhi, WRlo, NB, NB, NB, NB, P5, 6, 12};
        mma_raw<<<dim3(6, BATCH / 128, 2), blk, SMEM_TOT>>>(c0, c1, c0);
    }
    // M2: ht = mixture(x@L + rh@R + b) [mode 0: P1 + P2]
    {
        MArgs m0 = {x, rhp, P1, P2, b, htp, HID, gnode + 4 * HID, GN_LD, hthi, htlo, 0, 1};
        mixture3_kernel<<<dim3(mixGrid, 1, 1), 256>>>(Ws, m0, m0, m0);
    }
    // Batch D: ht@L -> P1 (reuse)
    {
        GR d0 = {hthi, htlo, WLhi, WLlo, NB, NB, NB, NB, P1, 6, 12};
        mma_raw<<<dim3(6, BATCH / 128, 1), blk, SMEM_TOT>>>(d0, d0, d0);
    }
    // M3: zht = mixture((ht@L)*(omz@R) + b) [mode 1: P1 * P5]
    {
        MArgs m0 = {htp, omzp, P1, P5, b, zhtp, HID, gnode + 6 * HID, GN_LD,
                    zhthi, zhtlo, 1, 3};
        mixture3_kernel<<<dim3(mixGrid, 1, 1), 256>>>(Ws, m0, m0, m0);
    }
    // Batch E (fused): zht@L + z2h@R -> P2 (NPAIR2, nch=24)
    {
        GR e0 = {zhthi, zhtlo, WLhi, WLlo, z2hhi, z2hlo, WRhi, WRlo, P2, 6, 24};
        mma_raw<<<dim3(6, BATCH / 128, 1), blk, SMEM_TOT>>>(e0, e0, e0);
    }
    // M4: h_next = mixture(P2 + b) [mode 5, pre-summed]
    {
        MArgs m0 = {zhtp, z2hp, P2, nullptr, b, out, HID, gnode + 8 * HID, GN_LD,
                    nullptr, nullptr, 5, 5};
        mixture3_kernel<<<dim3(mixGrid, 1, 1), 256>>>(Ws, m0, m0, m0);
    }

    finalize_kernel<<<1, 32>>>(out);
}

// round 17
// speedup vs baseline: 1.7424x; 1.7424x over previous
#include <cuda_runtime.h>
#include <cuda_bf16.h>
#include <math.h>
#include <stdint.h>

#define BATCH 16384
#define HID 256

// Output layout (float32):
//   [0, 4194304)            h_next  (B,1,256)
//   [4194304, 4194313)      G_structure (9 floats)
//   [4194313, 41943049)     G_node  (B,9,256)   <-- base NOT 16B-aligned (offset 9 floats)
//   [41943049, 41943055)    margins (6)
#define OFF_GS 4194304ul
#define OFF_GN 4194313ul
#define OFF_MG 41943049ul
#define GN_LD  2304

// ---------------------------------------------------------------------------
// Scratch (device globals). 16B-aligned (vector access).
//   P1: x@L -> ht@L        P2: h@R(512) -> r@R -> rh@R -> (zht@L + z2h@R) fused
//   P3: h@L                P4: z1@R
//   P5: omz@R
// ---------------------------------------------------------------------------
__device__ __align__(16) float g_p1[(size_t)BATCH * 768];
__device__ __align__(16) float g_p2[(size_t)BATCH * 768];
__device__ __align__(16) float g_p3[(size_t)BATCH * 768];
__device__ __align__(16) float g_p4[(size_t)BATCH * 768];
__device__ __align__(16) float g_p5[(size_t)BATCH * 768];
__device__ __align__(16) float g_z1 [(size_t)BATCH * HID];
__device__ __align__(16) float g_r  [(size_t)BATCH * HID];
__device__ __align__(16) float g_rh [(size_t)BATCH * HID];
__device__ __align__(16) float g_ht [(size_t)BATCH * HID];
__device__ __align__(16) float g_omz[(size_t)BATCH * HID];
__device__ __align__(16) float g_zht[(size_t)BATCH * HID];
__device__ __align__(16) float g_z2h[(size_t)BATCH * HID];
__device__ double g_ssum[24];

// split-bf16 activations (hi/lo)
#define ACT_ELEMS ((size_t)BATCH * HID)
__device__ __align__(16) __nv_bfloat16 g_xhi[ACT_ELEMS],  g_xlo[ACT_ELEMS];
__device__ __align__(16) __nv_bfloat16 g_hhi[ACT_ELEMS],  g_hlo[ACT_ELEMS];
__device__ __align__(16) __nv_bfloat16 g_z1hi[ACT_ELEMS], g_z1lo[ACT_ELEMS];
__device__ __align__(16) __nv_bfloat16 g_rhi[ACT_ELEMS],  g_rlo[ACT_ELEMS];
__device__ __align__(16) __nv_bfloat16 g_rhhi[ACT_ELEMS], g_rhlo[ACT_ELEMS];
__device__ __align__(16) __nv_bfloat16 g_hthi[ACT_ELEMS], g_htlo[ACT_ELEMS];
__device__ __align__(16) __nv_bfloat16 g_omzhi[ACT_ELEMS],g_omzlo[ACT_ELEMS];
__device__ __align__(16) __nv_bfloat16 g_zhthi[ACT_ELEMS],g_zhtlo[ACT_ELEMS];
__device__ __align__(16) __nv_bfloat16 g_z2hhi[ACT_ELEMS],g_z2hlo[ACT_ELEMS];

// split-bf16 weights, transposed [slab][n][k], slabs 0..2
#define W_ELEMS (3 * 65536)
__device__ __align__(16) __nv_bfloat16 g_WLhi[W_ELEMS], g_WLlo[W_ELEMS];
__device__ __align__(16) __nv_bfloat16 g_WRhi[W_ELEMS], g_WRlo[W_ELEMS];

__global__ void init_kernel() {
    int t = threadIdx.x;
    if (t < 24) g_ssum[t] = 0.0;
}

// W[s][k][n] fp32 -> hi/lo[s][n][k] bf16 (slabs 0..2); z: 0=L, 1=R
__global__ void prep_w(const float* __restrict__ WL, const float* __restrict__ WR,
                       __nv_bfloat16* __restrict__ hiL, __nv_bfloat16* __restrict__ loL,
                       __nv_bfloat16* __restrict__ hiR, __nv_bfloat16* __restrict__ loR) {
    const float* W = blockIdx.z ? WR : WL;
    __nv_bfloat16* hi = blockIdx.z ? hiR : hiL;
    __nv_bfloat16* lo = blockIdx.z ? loR : loL;
    int i = blockIdx.x * 256 + threadIdx.x;          // s*65536 + k*256 + n
    int s = i >> 16, rem = i & 65535, k = rem >> 8, n = rem & 255;
    float v = W[i];
    __nv_bfloat16 h = __float2bfloat16(v);
    size_t o = (size_t)s * 65536 + (size_t)n * 256 + k;
    hi[o] = h;
    lo[o] = __float2bfloat16(v - __bfloat162float(h));
}

// z: 0=x, 1=h
__global__ void prep_a(const float* __restrict__ X, const float* __restrict__ H,
                       __nv_bfloat16* __restrict__ xhi, __nv_bfloat16* __restrict__ xlo,
                       __nv_bfloat16* __restrict__ hhi, __nv_bfloat16* __restrict__ hlo) {
    const float* A = blockIdx.z ? H : X;
    __nv_bfloat16* hi = blockIdx.z ? hhi : xhi;
    __nv_bfloat16* lo = blockIdx.z ? hlo : xlo;
    size_t i = (size_t)blockIdx.x * 256 + threadIdx.x;
    float v = A[i];
    __nv_bfloat16 h = __float2bfloat16(v);
    hi[i] = h;
    lo[i] = __float2bfloat16(v - __bfloat162float(h));
}

// ---------------------------------------------------------------------------
// Raw tensor-core GEMM (bf16 mma.sync, fp32 accum), 3-term split:
//   C = Ahi@Whi + Alo@Whi + Ahi@Wlo   (12 chunks / operand pair)
// Optional second pair (nch=24) accumulates into the same output (fused
// zht@L + z2h@R). nx = active x-blocks (truncated N). Output raw fp32,
// ldc=768. CTA 128x128, 8 warps, 2-stage cp.async. blockIdx.z: arg set.
// ---------------------------------------------------------------------------
#define SROW 144
#define SAB  18432
#define SMEM_TOT (4 * SAB)

struct GR {
    const __nv_bfloat16 *Ahi, *Alo, *Bhi, *Blo;
    const __nv_bfloat16 *A2hi, *A2lo, *B2hi, *B2lo;
    float* C;
    int nx, nch;
};

__device__ __forceinline__ uint32_t smem_u32(const void* p) {
    uint32_t a;
    asm("{ .reg .u64 t; cvta.to.shared.u64 t, %1; cvt.u32.u64 %0, t; }" : "=r"(a) : "l"(p));
    return a;
}
#define CP_ASYNC16(dst, src) \
    asm volatile("cp.async.cg.shared.global [%0], [%1], 16;" :: "r"(dst), "l"(src))
#define CP_COMMIT() asm volatile("cp.async.commit_group;")
#define LDSM_X4(r, addr) \
    asm volatile("ldmatrix.sync.aligned.m8n8.x4.shared.b16 {%0,%1,%2,%3}, [%4];" \
        : "=r"((r)[0]), "=r"((r)[1]), "=r"((r)[2]), "=r"((r)[3]) : "r"(addr))
#define MMA16816(c, a, b0, b1) \
    asm volatile("mma.sync.aligned.m16n8k16.row.col.f32.bf16.bf16.f32 " \
        "{%0,%1,%2,%3}, {%4,%5,%6,%7}, {%8,%9}, {%0,%1,%2,%3};" \
        : "+f"((c)[0]), "+f"((c)[1]), "+f"((c)[2]), "+f"((c)[3]) \
        : "r"((a)[0]), "r"((a)[1]), "r"((a)[2]), "r"((a)[3]), "r"(b0), "r"(b1))

__global__ void __launch_bounds__(256, 2) mma_raw(GR g0, GR g1, GR g2)
{
    const GR& G = (blockIdx.z == 0) ? g0 : (blockIdx.z == 1) ? g1 : g2;
    if ((int)blockIdx.x >= G.nx) return;
    extern __shared__ __align__(16) char smem[];
    const int tid = threadIdx.x, wid = tid >> 5, lane = tid & 31;
    const int wm = wid >> 2, wn = wid & 3;
    const int bm0 = blockIdx.y * 128;
    const int nglob = blockIdx.x * 128;
    const int slab = nglob >> 8, nr = nglob & 255;
    const uint32_t sb = smem_u32(smem);
    const int NCH = G.nch;

    const int lr = tid >> 1, lh = tid & 1;
    const size_t gArow = (size_t)(bm0 + lr) * 256 + lh * 32;
    const size_t gBrow = (size_t)slab * 65536 + (size_t)(nr + lr) * 256 + lh * 32;
    const uint32_t sOff = lr * SROW + lh * 64;

    auto issue = [&](int c) {
        const int p = (c >= 12) ? 1 : 0;
        const int cc = c - 12 * p;
        const int seg = cc >> 2;
        const int k0 = (cc & 3) * 64;
        const __nv_bfloat16* gA = (seg == 1) ? (p ? G.A2lo : G.Alo) : (p ? G.A2hi : G.Ahi);
        const __nv_bfloat16* gB = (seg == 2) ? (p ? G.B2lo : G.Blo) : (p ? G.B2hi : G.Bhi);
        const char* srcA = (const char*)(gA + gArow + k0);
        const char* srcB = (const char*)(gB + gBrow + k0);
        const int buf = c & 1;
        uint32_t dA = sb + buf * 2 * SAB + sOff;
        uint32_t dB = sb + buf * 2 * SAB + SAB + sOff;
        #pragma unroll
        for (int i = 0; i < 4; i++) CP_ASYNC16(dA + i * 16, srcA + i * 16);
        #pragma unroll
        for (int i = 0; i < 4; i++) CP_ASYNC16(dB + i * 16, srcB + i * 16);
    };

    float acc[4][4][4];
    #pragma unroll
    for (int i = 0; i < 4; i++)
        #pragma unroll
        for (int j = 0; j < 4; j++)
            #pragma unroll
            for (int t = 0; t < 4; t++) acc[i][j][t] = 0.f;

    const uint32_t aLane = (lane & 15) * SROW + (lane >> 4) * 16;
    const uint32_t bLane = ((lane & 7) + ((lane >= 16) ? 8 : 0)) * SROW + ((lane >> 3) & 1) * 16;

    issue(0); CP_COMMIT();

    #pragma unroll 1
    for (int c = 0; c < NCH; c++) {
        asm volatile("cp.async.wait_group 0;");
        __syncthreads();
        if (c + 1 < NCH) { issue(c + 1); CP_COMMIT(); }

        const int buf = c & 1;
        const uint32_t aBase = sb + buf * 2 * SAB + (wm * 64) * SROW + aLane;
        const uint32_t bBase = sb + buf * 2 * SAB + SAB + (wn * 32) * SROW + bLane;

        uint32_t a[2][4][4], bfr[2][2][4];
        #pragma unroll
        for (int np = 0; np < 2; np++)
            LDSM_X4(bfr[0][np], bBase + np * 16 * SROW);
        #pragma unroll
        for (int mt = 0; mt < 4; mt++)
            LDSM_X4(a[0][mt], aBase + mt * 16 * SROW);

        #pragma unroll
        for (int ks = 0; ks < 4; ks++) {
            const int cur = ks & 1, nxt = cur ^ 1;
            if (ks < 3) {
                #pragma unroll
                for (int np = 0; np < 2; np++)
                    LDSM_X4(bfr[nxt][np], bBase + np * 16 * SROW + (ks + 1) * 32);
                #pragma unroll
                for (int mt = 0; mt < 4; mt++)
                    LDSM_X4(a[nxt][mt], aBase + mt * 16 * SROW + (ks + 1) * 32);
            }
            #pragma unroll
            for (int mt = 0; mt < 4; mt++)
                #pragma unroll
                for (int nt = 0; nt < 4; nt++)
                    MMA16816(acc[mt][nt], a[cur][mt],
                             bfr[cur][nt >> 1][(nt & 1) * 2],
                             bfr[cur][nt >> 1][(nt & 1) * 2 + 1]);
        }
    }

    // Epilogue: raw fp32 store, ldc=768
    const int lr4 = lane >> 2, lc2 = (lane & 3) * 2;
    #pragma unroll
    for (int mt = 0; mt < 4; mt++) {
        #pragma unroll
        for (int nt = 0; nt < 4; nt++) {
            const int row0 = bm0 + wm * 64 + mt * 16 + lr4;
            const int gcol = nglob + wn * 32 + nt * 8 + lc2;
            #pragma unroll
            for (int half = 0; half < 2; half++) {
                const int row = row0 + half * 8;
                float2 v = make_float2(acc[mt][nt][half * 2 + 0],
                                       acc[mt][nt][half * 2 + 1]);
                *(float2*)(G.C + (size_t)row * 768 + gcol) = v;
            }
        }
    }
}

// ---------------------------------------------------------------------------
// z1 & r from raw product slices (vectorized: 4 elems/thread).
// ---------------------------------------------------------------------------
__global__ void __launch_bounds__(256) z1r_kernel(
    const float* __restrict__ xL, const float* __restrict__ hR,
    const float* __restrict__ bias, float* __restrict__ gnode)
{
    // 64 threads per row, 4 rows per block; each thread does 4 contiguous elems
    int tid = threadIdx.x;
    size_t b_ = (size_t)blockIdx.x * 4 + (tid >> 6);
    int d0 = (tid & 63) * 4;
    size_t base = b_ * 768;

    float4 xa = *(const float4*)(xL + base + d0);
    float4 ha = *(const float4*)(hR + base + d0);
    float4 ba = *(const float4*)(bias + d0);
    float4 xb = *(const float4*)(xL + base + 256 + d0);
    float4 hb = *(const float4*)(hR + base + 256 + d0);
    float4 bb = *(const float4*)(bias + 256 + d0);

    float z[4], r[4];
    z[0] = 1.f / (1.f + expf(-(xa.x + ha.x + ba.x)));
    z[1] = 1.f / (1.f + expf(-(xa.y + ha.y + ba.y)));
    z[2] = 1.f / (1.f + expf(-(xa.z + ha.z + ba.z)));
    z[3] = 1.f / (1.f + expf(-(xa.w + ha.w + ba.w)));
    r[0] = 1.f / (1.f + expf(-(xb.x + hb.x + bb.x)));
    r[1] = 1.f / (1.f + expf(-(xb.y + hb.y + bb.y)));
    r[2] = 1.f / (1.f + expf(-(xb.z + hb.z + bb.z)));
    r[3] = 1.f / (1.f + expf(-(xb.w + hb.w + bb.w)));

    *(float4*)(g_z1 + b_ * HID + d0) = make_float4(z[0], z[1], z[2], z[3]);
    *(float4*)(g_r  + b_ * HID + d0) = make_float4(r[0], r[1], r[2], r[3]);

    float* gn = gnode + b_ * GN_LD;
    #pragma unroll
    for (int j = 0; j < 4; j++) {          // G_node mirrors: scalar (misaligned base)
        gn[0 * HID + d0 + j] = z[j];
        gn[2 * HID + d0 + j] = z[j];
        gn[1 * HID + d0 + j] = r[j];
    }

    uint2 zh, rh2;
    __nv_bfloat16 h0, h1;
    uint2 zl, rl2;
    h0 = __float2bfloat16(z[0]); h1 = __float2bfloat16(z[1]);
    zh.x = ((uint32_t)*(uint16_t*)&h1 << 16) | *(uint16_t*)&h0;
    { __nv_bfloat16 l0 = __float2bfloat16(z[0] - __bfloat162float(h0));
      __nv_bfloat16 l1 = __float2bfloat16(z[1] - __bfloat162float(h1));
      zl.x = ((uint32_t)*(uint16_t*)&l1 << 16) | *(uint16_t*)&l0; }
    h0 = __float2bfloat16(z[2]); h1 = __float2bfloat16(z[3]);
    zh.y = ((uint32_t)*(uint16_t*)&h1 << 16) | *(uint16_t*)&h0;
    { __nv_bfloat16 l0 = __float2bfloat16(z[2] - __bfloat162float(h0));
      __nv_bfloat16 l1 = __float2bfloat16(z[3] - __bfloat162float(h1));
      zl.y = ((uint32_t)*(uint16_t*)&l1 << 16) | *(uint16_t*)&l0; }
    h0 = __float2bfloat16(r[0]); h1 = __float2bfloat16(r[1]);
    rh2.x = ((uint32_t)*(uint16_t*)&h1 << 16) | *(uint16_t*)&h0;
    { __nv_bfloat16 l0 = __float2bfloat16(r[0] - __bfloat162float(h0));
      __nv_bfloat16 l1 = __float2bfloat16(r[1] - __bfloat162float(h1));
      rl2.x = ((uint32_t)*(uint16_t*)&l1 << 16) | *(uint16_t*)&l0; }
    h0 = __float2bfloat16(r[2]); h1 = __float2bfloat16(r[3]);
    rh2.y = ((uint32_t)*(uint16_t*)&h1 << 16) | *(uint16_t*)&h0;
    { __nv_bfloat16 l0 = __float2bfloat16(r[2] - __bfloat162float(h0));
      __nv_bfloat16 l1 = __float2bfloat16(r[3] - __bfloat162float(h1));
      rl2.y = ((uint32_t)*(uint16_t*)&l1 << 16) | *(uint16_t*)&l0; }
    *(uint2*)(g_z1hi + b_ * HID + d0) = zh;
    *(uint2*)(g_z1lo + b_ * HID + d0) = zl;
    *(uint2*)(g_rhi + b_ * HID + d0) = rh2;
    *(uint2*)(g_rlo + b_ * HID + d0) = rl2;
}

// ---------------------------------------------------------------------------
// Mixture over 4 candidates from RAW product buffers. VECTORIZED: one warp
// per row, lane owns 8 CONTIGUOUS elems (d = lane*8+j), float4 loads/stores.
//   mode 0: c[k] = cand[k] + cand2[k] + ball[k];  k3 = a1 + a2 + b3
//   mode 1: c[k] = cand[k] * cand2[k] + ball[k];  k3 = a1*a2 + b3
//   mode 4: c[k] = 1 - (cand[k] + ball[k]);       k3 = 1 - (a1 + b3)
//   mode 5: c[k] = cand[k] + ball[k] (pre-summed);k3 = a1 + a2 + b3
// ---------------------------------------------------------------------------
struct MArgs {
    const float *A1, *A2, *cand, *cand2, *ball;
    float* out1; int ld1;
    float* out2; int ld2;
    __nv_bfloat16 *Ohi, *Olo;
    int mode, stage;
};

__global__ void __launch_bounds__(256) mixture3_kernel(
    const float* __restrict__ Wsv, MArgs m0, MArgs m1, MArgs m2)
{
    const MArgs& M = (blockIdx.z == 0) ? m0 : (blockIdx.z == 1) ? m1 : m2;
    __shared__ float sWs[256];
    __shared__ float sSc[8][4];
    int tid = threadIdx.x;
    sWs[tid] = Wsv[tid];
    __syncthreads();

    int warp = tid >> 5, lane = tid & 31;
    size_t b = (size_t)blockIdx.x * 8 + warp;
    const int d0 = lane * 8;
    const float* crow  = M.cand + b * 768;
    const float* crow2 = (M.mode <= 1) ? (M.cand2 + b * 768) : nullptr;

    float wv[8];
    { float4 w0 = *(const float4*)&sWs[d0];
      float4 w1 = *(const float4*)&sWs[d0 + 4];
      wv[0]=w0.x; wv[1]=w0.y; wv[2]=w0.z; wv[3]=w0.w;
      wv[4]=w1.x; wv[5]=w1.y; wv[6]=w1.z; wv[7]=w1.w; }

    float c[4][8];
    #pragma unroll
    for (int k = 0; k < 3; k++) {
        #pragma unroll
        for (int q = 0; q < 2; q++) {
            float4 v4 = *(const float4*)(crow + k * 256 + d0 + q * 4);
            float4 b4 = *(const float4*)(M.ball + k * 256 + d0 + q * 4);
            float* vp = &v4.x; float* bp = &b4.x;
            if (M.mode <= 1) {
                float4 u4 = *(const float4*)(crow2 + k * 256 + d0 + q * 4);
                float* up = &u4.x;
                #pragma unroll
                for (int j = 0; j < 4; j++)
                    c[k][q * 4 + j] = (M.mode == 0) ? (vp[j] + up[j] + bp[j])
                                                    : fmaf(vp[j], up[j], bp[j]);
            } else if (M.mode == 4) {
                #pragma unroll
                for (int j = 0; j < 4; j++) c[k][q * 4 + j] = 1.f - (vp[j] + bp[j]);
            } else {
                #pragma unroll
                for (int j = 0; j < 4; j++) c[k][q * 4 + j] = vp[j] + bp[j];
            }
        }
    }
    #pragma unroll
    for (int q = 0; q < 2; q++) {
        float4 a4 = *(const float4*)(M.A1 + b * HID + d0 + q * 4);
        float4 b4 = *(const float4*)(M.ball + 768 + d0 + q * 4);
        float* ap = &a4.x; float* bp = &b4.x;
        if (M.mode == 0 || M.mode == 5) {
            float4 a24 = *(const float4*)(M.A2 + b * HID + d0 + q * 4);
            float* a2p = &a24.x;
            #pragma unroll
            for (int j = 0; j < 4; j++) c[3][q * 4 + j] = ap[j] + a2p[j] + bp[j];
        } else if (M.mode == 1) {
            float4 a24 = *(const float4*)(M.A2 + b * HID + d0 + q * 4);
            float* a2p = &a24.x;
            #pragma unroll
            for (int j = 0; j < 4; j++) c[3][q * 4 + j] = fmaf(ap[j], a2p[j], bp[j]);
        } else {
            #pragma unroll
            for (int j = 0; j < 4; j++) c[3][q * 4 + j] = 1.f - (ap[j] + bp[j]);
        }
    }

    float sc[4];
    #pragma unroll
    for (int k = 0; k < 4; k++) {
        float p = 0.f;
        #pragma unroll
        for (int j = 0; j < 8; j++) p = fmaf(c[k][j], wv[j], p);
        #pragma unroll
        for (int o = 16; o > 0; o >>= 1) p += __shfl_xor_sync(0xffffffffu, p, o);
        sc[k] = p;
    }

    float mx = fmaxf(fmaxf(sc[0], sc[1]), fmaxf(sc[2], sc[3]));
    float e0 = expf(sc[0] - mx), e1 = expf(sc[1] - mx);
    float e2 = expf(sc[2] - mx), e3 = expf(sc[3] - mx);
    float inv = 1.f / (e0 + e1 + e2 + e3);

    float o8[8];
    #pragma unroll
    for (int j = 0; j < 8; j++)
        o8[j] = (e0 * c[0][j] + e1 * c[1][j] + e2 * c[2][j] + e3 * c[3][j]) * inv;

    // out1: 16B-aligned targets (scratch or d_out base) -> float4
    *(float4*)(M.out1 + b * M.ld1 + d0)     = make_float4(o8[0], o8[1], o8[2], o8[3]);
    *(float4*)(M.out1 + b * M.ld1 + d0 + 4) = make_float4(o8[4], o8[5], o8[6], o8[7]);
    if (M.out2) {                            // G_node mirror: scalar (misaligned base)
        float* p2 = M.out2 + b * M.ld2 + d0;
        #pragma unroll
        for (int j = 0; j < 8; j++) p2[j] = o8[j];
    }
    if (M.Ohi) {
        uint4 hv, lv;
        uint32_t* hp = &hv.x; uint32_t* lp = &lv.x;
        #pragma unroll
        for (int q = 0; q < 4; q++) {
            __nv_bfloat16 h0 = __float2bfloat16(o8[q * 2]);
            __nv_bfloat16 h1 = __float2bfloat16(o8[q * 2 + 1]);
            hp[q] = ((uint32_t)*(uint16_t*)&h1 << 16) | *(uint16_t*)&h0;
            __nv_bfloat16 l0 = __float2bfloat16(o8[q * 2] - __bfloat162float(h0));
            __nv_bfloat16 l1 = __float2bfloat16(o8[q * 2 + 1] - __bfloat162float(h1));
            lp[q] = ((uint32_t)*(uint16_t*)&l1 << 16) | *(uint16_t*)&l0;
        }
        *(uint4*)(M.Ohi + b * HID + d0) = hv;
        *(uint4*)(M.Olo + b * HID + d0) = lv;
    }

    if (lane == 0) {
        sSc[warp][0] = sc[0]; sSc[warp][1] = sc[1];
        sSc[warp][2] = sc[2]; sSc[warp][3] = sc[3];
    }
    __syncthreads();
    if (tid < 4) {
        float s = 0.f;
        #pragma unroll
        for (int w = 0; w < 8; w++) s += sSc[w][tid];
        atomicAdd(&g_ssum[M.stage * 4 + tid], (double)s);
    }
}

__global__ void finalize_kernel(float* __restrict__ out) {
    if (threadIdx.x == 0 && blockIdx.x == 0) {
        float* gs = out + OFF_GS;
        float* mg = out + OFF_MG;
        gs[0] = 0.f; gs[1] = 1.f; gs[2] = 0.f;
        for (int s = 0; s < 6; s++) {
            double v[4];
            for (int k = 0; k < 4; k++) v[k] = g_ssum[s * 4 + k];
            int idx = 0; double m1 = v[0];
            for (int k = 1; k < 4; k++) if (v[k] > m1) { m1 = v[k]; idx = k; }
            double m2 = -1e300;
            for (int k = 0; k < 4; k++) if (k != idx && v[k] > m2) m2 = v[k];
            gs[3 + s] = (float)idx;
            mg[s] = (float)(m1 - m2);
        }
    }
}

// ---------------------------------------------------------------------------
extern "C" void kernel_launch(void* const* d_in, const int* in_sizes, int n_in,
                              void* d_out, int out_size) {
    const float* x  = (const float*)d_in[0];
    const float* h  = (const float*)d_in[1];
    const float* L  = (const float*)d_in[2];
    const float* R  = (const float*)d_in[3];
    const float* b  = (const float*)d_in[4];
    const float* Ws = (const float*)d_in[5];
    float* out = (float*)d_out;
    float* gnode = out + OFF_GN;

    float *z1p, *rp, *rhp, *htp, *omzp, *zhtp, *z2hp, *P1, *P2, *P3, *P4, *P5;
    cudaGetSymbolAddress((void**)&z1p,  g_z1);
    cudaGetSymbolAddress((void**)&rp,   g_r);
    cudaGetSymbolAddress((void**)&rhp,  g_rh);
    cudaGetSymbolAddress((void**)&htp,  g_ht);
    cudaGetSymbolAddress((void**)&omzp, g_omz);
    cudaGetSymbolAddress((void**)&zhtp, g_zht);
    cudaGetSymbolAddress((void**)&z2hp, g_z2h);
    cudaGetSymbolAddress((void**)&P1, g_p1);
    cudaGetSymbolAddress((void**)&P2, g_p2);
    cudaGetSymbolAddress((void**)&P3, g_p3);
    cudaGetSymbolAddress((void**)&P4, g_p4);
    cudaGetSymbolAddress((void**)&P5, g_p5);

    __nv_bfloat16 *xhi,*xlo,*hhi,*hlo,*z1hi,*z1lo,*rhi,*rlo,*rhhi,*rhlo,
                  *hthi,*htlo,*omzhi,*omzlo,*zhthi,*zhtlo,*z2hhi,*z2hlo,
                  *WLhi,*WLlo,*WRhi,*WRlo;
    cudaGetSymbolAddress((void**)&xhi, g_xhi);   cudaGetSymbolAddress((void**)&xlo, g_xlo);
    cudaGetSymbolAddress((void**)&hhi, g_hhi);   cudaGetSymbolAddress((void**)&hlo, g_hlo);
    cudaGetSymbolAddress((void**)&z1hi, g_z1hi); cudaGetSymbolAddress((void**)&z1lo, g_z1lo);
    cudaGetSymbolAddress((void**)&rhi, g_rhi);   cudaGetSymbolAddress((void**)&rlo, g_rlo);
    cudaGetSymbolAddress((void**)&rhhi, g_rhhi); cudaGetSymbolAddress((void**)&rhlo, g_rhlo);
    cudaGetSymbolAddress((void**)&hthi, g_hthi); cudaGetSymbolAddress((void**)&htlo, g_htlo);
    cudaGetSymbolAddress((void**)&omzhi, g_omzhi); cudaGetSymbolAddress((void**)&omzlo, g_omzlo);
    cudaGetSymbolAddress((void**)&zhthi, g_zhthi); cudaGetSymbolAddress((void**)&zhtlo, g_zhtlo);
    cudaGetSymbolAddress((void**)&z2hhi, g_z2hhi); cudaGetSymbolAddress((void**)&z2hlo, g_z2hlo);
    cudaGetSymbolAddress((void**)&WLhi, g_WLhi); cudaGetSymbolAddress((void**)&WLlo, g_WLlo);
    cudaGetSymbolAddress((void**)&WRhi, g_WRhi); cudaGetSymbolAddress((void**)&WRlo, g_WRlo);

    cudaFuncSetAttribute(mma_raw, cudaFuncAttributeMaxDynamicSharedMemorySize, SMEM_TOT);

    dim3 blk(256);
    int mixGrid = BATCH / 8;

    init_kernel<<<1, 32>>>();
    prep_w<<<dim3(768, 1, 2), 256>>>(L, R, WLhi, WLlo, WRhi, WRlo);
    prep_a<<<dim3(BATCH * HID / 256, 1, 2), 256>>>(x, h, xhi, xlo, hhi, hlo);

    const __nv_bfloat16* NB = nullptr;

    // Batch A: x@L -> P1 (full), h@R -> P2 (slabs 0,1), h@L -> P3 (full)
    {
        GR a0 = {xhi, xlo, WLhi, WLlo, NB, NB, NB, NB, P1, 6, 12};
        GR a1 = {hhi, hlo, WRhi, WRlo, NB, NB, NB, NB, P2, 4, 12};
        GR a2 = {hhi, hlo, WLhi, WLlo, NB, NB, NB, NB, P3, 6, 12};
        mma_raw<<<dim3(6, BATCH / 128, 3), blk, SMEM_TOT>>>(a0, a1, a2);
    }
    // z1 & r from slices of P1/P2
    z1r_kernel<<<BATCH / 4, 256>>>(P1, P2, b, gnode);

    // Batch B: r@R -> P2 (reuse), z1@R -> P4
    {
        GR b0 = {rhi, rlo, WRhi, WRlo, NB, NB, NB, NB, P2, 6, 12};
        GR b1 = {z1hi, z1lo, WRhi, WRlo, NB, NB, NB, NB, P4, 6, 12};
        mma_raw<<<dim3(6, BATCH / 128, 2), blk, SMEM_TOT>>>(b0, b1, b0);
    }
    // M1 (3 slices): rh [P3+P2], omz [1-(P4+b)], z2h [P3*P4]
    {
        MArgs m0 = {h, rp, P3, P2, b, rhp, HID, gnode + 3 * HID, GN_LD, rhhi, rhlo, 0, 0};
        MArgs m1 = {z1p, nullptr, P4, nullptr, b, omzp, HID, gnode + 5 * HID, GN_LD,
                    omzhi, omzlo, 4, 2};
        MArgs m2 = {h, z1p, P3, P4, b, z2hp, HID, gnode + 7 * HID, GN_LD,
                    z2hhi, z2hlo, 1, 4};
        mixture3_kernel<<<dim3(mixGrid, 1, 3), 256>>>(Ws, m0, m1, m2);
    }
    // Batch C: rh@R -> P2 (reuse), omz@R -> P5
    {
        GR c0 = {rhhi, rhlo, WRhi, WRlo, NB, NB, NB, NB, P2, 6, 12};
        GR c1 = {omzhi, omzlo, WRhi, WRlo, NB, NB, NB, NB, P5, 6, 12};
        mma_raw<<<dim3(6, BATCH / 128, 2), blk, SMEM_TOT>>>(c0, c1, c0);
    }
    // M2: ht = mixture(x@L + rh@R + b) [mode 0: P1 + P2]
    {
        MArgs m0 = {x, rhp, P1, P2, b, htp, HID, gnode + 4 * HID, GN_LD, hthi, htlo, 0, 1};
        mixture3_kernel<<<dim3(mixGrid, 1, 1), 256>>>(Ws, m0, m0, m0);
    }
    // Batch D: ht@L -> P1 (reuse)
    {
        GR d0 = {hthi, htlo, WLhi, WLlo, NB, NB, NB, NB, P1, 6, 12};
        mma_raw<<<dim3(6, BATCH / 128, 1), blk, SMEM_TOT>>>(d0, d0, d0);
    }
    // M3: zht = mixture((ht@L)*(omz@R) + b) [mode 1: P1 * P5]
    {
        MArgs m0 = {htp, omzp, P1, P5, b, zhtp, HID, gnode + 6 * HID, GN_LD,
                    zhthi, zhtlo, 1, 3};
        mixture3_kernel<<<dim3(mixGrid, 1, 1), 256>>>(Ws, m0, m0, m0);
    }
    // Batch E (fused): zht@L + z2h@R -> P2 (nch=24)
    {
        GR e0 = {zhthi, zhtlo, WLhi, WLlo, z2hhi, z2hlo, WRhi, WRlo, P2, 6, 24};
        mma_raw<<<dim3(6, BATCH / 128, 1), blk, SMEM_TOT>>>(e0, e0, e0);
    }
    // M4: h_next = mixture(P2 + b) [mode 5, pre-summed]
    {
        MArgs m0 = {zhtp, z2hp, P2, nullptr, b, out, HID, gnode + 8 * HID, GN_LD,
                    nullptr, nullptr, 5, 5};
        mixture3_kernel<<<dim3(mixGrid, 1, 1), 256>>>(Ws, m0, m0, m0);
    }

    finalize_kernel<<<1, 32>>>(out);
}